// round 5
// baseline (speedup 1.0000x reference)
#include <cuda_runtime.h>

// Problem constants
#define N_NODES 50000
#define D 256
#define E_EDGES 150000
#define M_DIR (2 * E_EDGES)
#define INV_SCALE 0.125f   // 1/sqrt(64)

// -------- scratch (device globals; no allocations allowed) --------
// Phase 1: g_TV[r] holds T_r = S @ P_r      (used by k_score)
// Phase 2: g_TV[r] holds V_r = S @ W_r^T    (used by k_agg) — same storage, reused
__device__ float g_TV[3][N_NODES * D];  // ~154 MB
__device__ float g_P[3][D * D];         // P_r[m][k] = sum_c WQ[c][k] * WK[c][m]
__device__ float g_Ee[3][M_DIR];        // exp(score) per directed edge
__device__ float g_z[3][N_NODES];       // softmax denominators

// -------- K0: zero output + z --------
__global__ void k_init(float* __restrict__ out) {
    int i = blockIdx.x * blockDim.x + threadIdx.x;
    if (i < N_NODES * D) out[i] = 0.0f;
    if (i < 3 * N_NODES) (&g_z[0][0])[i] = 0.0f;
}

// -------- K1: P_r = WQ^T @ WK  (stored as P[m][k], k-contiguous) --------
// P[m][k] = sum_c WQ[c*D + k] * WK[c*D + m]
__global__ void k_mat(const float* __restrict__ WQ, const float* __restrict__ WK) {
    int r = blockIdx.z;
    int mBase = blockIdx.y * 16, kBase = blockIdx.x * 16;
    int ty = threadIdx.y, tx = threadIdx.x;
    __shared__ float aq[16][17];   // aq[cc][kk]
    __shared__ float ak[16][17];   // ak[cc][mm]
    const float* wq = WQ + r * D * D;
    const float* wk = WK + r * D * D;
    float acc = 0.0f;
    for (int c0 = 0; c0 < D; c0 += 16) {
        aq[ty][tx] = wq[(c0 + ty) * D + kBase + tx];
        ak[ty][tx] = wk[(c0 + ty) * D + mBase + tx];
        __syncthreads();
#pragma unroll
        for (int cc = 0; cc < 16; cc++)
            acc += ak[cc][ty] * aq[cc][tx];
        __syncthreads();
    }
    g_P[r][(mBase + ty) * D + kBase + tx] = acc;
}

// -------- K2: big GEMMs. mode=0: T_r = S @ P_r (k-contig); mode=1: V_r = S @ W_r^T --------
#define BM 128
#define BN 128
#define BK 16
#define TM 8
#define TN 8

__global__ void __launch_bounds__(256) k_gemm(const float* __restrict__ S,
                                              const float* __restrict__ W,
                                              int mode) {
    int r = blockIdx.z;
    const float* B = (mode == 0) ? g_P[r] : (W + (size_t)r * D * D);
    float* C = g_TV[r];

    int rowBase = blockIdx.x * BM;
    int colBase = blockIdx.y * BN;

    __shared__ float As[BK][BM];
    __shared__ float Bs[BK][BN];

    int tid  = threadIdx.x;
    int tRow = tid / 16;       // 0..15
    int tCol = tid % 16;       // 0..15

    // loaders: 256 threads, each loads 2 float4 per tile (BK=16 -> 128*16 floats = 512 float4)
    int ldRow = tid >> 2;          // 0..63
    int ldK4  = (tid & 3) * 4;     // 0,4,8,12

    float acc[TM][TN] = {};

    for (int k0 = 0; k0 < D; k0 += BK) {
#pragma unroll
        for (int half = 0; half < 2; half++) {
            int row = ldRow + half * 64;
            float4 av = make_float4(0.f, 0.f, 0.f, 0.f);
            int gr = rowBase + row;
            if (gr < N_NODES) av = *(const float4*)(S + (size_t)gr * D + k0 + ldK4);
            As[ldK4 + 0][row] = av.x;
            As[ldK4 + 1][row] = av.y;
            As[ldK4 + 2][row] = av.z;
            As[ldK4 + 3][row] = av.w;

            float4 bv = *(const float4*)(B + (size_t)(colBase + row) * D + k0 + ldK4);
            Bs[ldK4 + 0][row] = bv.x;
            Bs[ldK4 + 1][row] = bv.y;
            Bs[ldK4 + 2][row] = bv.z;
            Bs[ldK4 + 3][row] = bv.w;
        }
        __syncthreads();

#pragma unroll
        for (int kk = 0; kk < BK; kk++) {
            float ra[TM], rb[TN];
#pragma unroll
            for (int i = 0; i < TM; i++) ra[i] = As[kk][tRow * TM + i];
#pragma unroll
            for (int j = 0; j < TN; j++) rb[j] = Bs[kk][tCol * TN + j];
#pragma unroll
            for (int i = 0; i < TM; i++)
#pragma unroll
                for (int j = 0; j < TN; j++)
                    acc[i][j] += ra[i] * rb[j];
        }
        __syncthreads();
    }

#pragma unroll
    for (int i = 0; i < TM; i++) {
        int gr = rowBase + tRow * TM + i;
        if (gr >= N_NODES) break;
        float4 v0 = make_float4(acc[i][0], acc[i][1], acc[i][2], acc[i][3]);
        float4 v1 = make_float4(acc[i][4], acc[i][5], acc[i][6], acc[i][7]);
        *(float4*)(C + (size_t)gr * D + colBase + tCol * TN)     = v0;
        *(float4*)(C + (size_t)gr * D + colBase + tCol * TN + 4) = v1;
    }
}

// -------- K3: per undirected edge: both directional scores, exp, z accumulation --------
// Reads T from g_TV (phase 1 contents).
__global__ void __launch_bounds__(256) k_score(const float* __restrict__ S,
                                               const int* __restrict__ e_t,
                                               const int* __restrict__ e_c,
                                               const int* __restrict__ e_s) {
    int r = blockIdx.y;
    const int* edges = (r == 0) ? e_t : (r == 1) ? e_c : e_s;
    int warp = blockIdx.x * (blockDim.x >> 5) + (threadIdx.x >> 5);
    int lane = threadIdx.x & 31;
    if (warp >= E_EDGES) return;

    int a = edges[2 * warp];
    int b = edges[2 * warp + 1];
    const float* T  = g_TV[r];
    const float* Ta = T + (size_t)a * D;
    const float* Tb = T + (size_t)b * D;
    const float* Sa = S + (size_t)a * D;
    const float* Sb = S + (size_t)b * D;

    float s_ab = 0.f, s_ba = 0.f;
#pragma unroll
    for (int c = 0; c < 2; c++) {
        int d = c * 128 + lane * 4;
        float4 ta = *(const float4*)(Ta + d);
        float4 sb = *(const float4*)(Sb + d);
        float4 tb = *(const float4*)(Tb + d);
        float4 sa = *(const float4*)(Sa + d);
        s_ab += ta.x * sb.x + ta.y * sb.y + ta.z * sb.z + ta.w * sb.w;
        s_ba += tb.x * sa.x + tb.y * sa.y + tb.z * sa.z + tb.w * sa.w;
    }
#pragma unroll
    for (int o = 16; o > 0; o >>= 1) {
        s_ab += __shfl_xor_sync(0xffffffff, s_ab, o);
        s_ba += __shfl_xor_sync(0xffffffff, s_ba, o);
    }
    if (lane == 0) {
        // Scores are N(0, ~1.3): |s*INV_SCALE| << 80, exp() safe without max-subtraction
        float eab = expf(s_ab * INV_SCALE);
        float eba = expf(s_ba * INV_SCALE);
        g_Ee[r][warp]           = eab;   // direction rec=a, nbr=b
        g_Ee[r][E_EDGES + warp] = eba;   // direction rec=b, nbr=a
        atomicAdd(&g_z[r][a], eab);
        atomicAdd(&g_z[r][b], eba);
    }
}

// -------- K4: aggregation: out[rec] += alpha * V[nbr] (vector atomics) --------
// Reads V from g_TV (phase 2 contents).
__global__ void __launch_bounds__(256) k_agg(float* __restrict__ out,
                                             const int* __restrict__ e_t,
                                             const int* __restrict__ e_c,
                                             const int* __restrict__ e_s) {
    int r = blockIdx.y;
    const int* edges = (r == 0) ? e_t : (r == 1) ? e_c : e_s;
    int warp = blockIdx.x * (blockDim.x >> 5) + (threadIdx.x >> 5);
    int lane = threadIdx.x & 31;
    if (warp >= M_DIR) return;

    int rec, nbr;
    if (warp < E_EDGES) {
        rec = edges[2 * warp];
        nbr = edges[2 * warp + 1];
    } else {
        int e = warp - E_EDGES;
        rec = edges[2 * e + 1];
        nbr = edges[2 * e];
    }
    float alpha = g_Ee[r][warp] / g_z[r][rec];

    const float* V = g_TV[r] + (size_t)nbr * D;
    float* O = out + (size_t)rec * D;
#pragma unroll
    for (int c = 0; c < 2; c++) {
        int d = c * 128 + lane * 4;
        float4 v = *(const float4*)(V + d);
        float4 addv = make_float4(alpha * v.x, alpha * v.y, alpha * v.z, alpha * v.w);
        atomicAdd((float4*)(O + d), addv);
    }
}

// -------- K5: relu in place --------
__global__ void k_relu(float* __restrict__ out) {
    int i = blockIdx.x * blockDim.x + threadIdx.x;
    if (i < N_NODES * D) out[i] = fmaxf(out[i], 0.0f);
}

extern "C" void kernel_launch(void* const* d_in, const int* in_sizes, int n_in,
                              void* d_out, int out_size) {
    const float* S  = (const float*)d_in[0];
    const int*   et = (const int*)d_in[1];
    const int*   ec = (const int*)d_in[2];
    const int*   es = (const int*)d_in[3];
    const float* W  = (const float*)d_in[4];
    const float* WQ = (const float*)d_in[5];
    const float* WK = (const float*)d_in[6];
    float* out = (float*)d_out;

    // K0: zero out + z
    k_init<<<(N_NODES * D + 255) / 256, 256>>>(out);

    // K1: P_r = WQ_r^T @ WK_r (tiny)
    {
        dim3 g(D / 16, D / 16, 3), b(16, 16);
        k_mat<<<g, b>>>(WQ, WK);
    }

    dim3 gg((N_NODES + BM - 1) / BM, D / BN, 3);

    // K2a: T_r = S @ P_r  (into g_TV)
    k_gemm<<<gg, 256>>>(S, W, 0);

    // K3: edge scores -> exp -> z (consumes T)
    {
        dim3 g((E_EDGES + 7) / 8, 3);   // 8 warps per 256-thread block
        k_score<<<g, 256>>>(S, et, ec, es);
    }

    // K2b: V_r = S @ W_r^T (overwrites g_TV — T no longer needed)
    k_gemm<<<gg, 256>>>(S, W, 1);

    // K4: weighted aggregation (consumes V)
    {
        dim3 g((M_DIR + 7) / 8, 3);
        k_agg<<<g, 256>>>(out, et, ec, es);
    }

    // K5: relu
    k_relu<<<(N_NODES * D + 255) / 256, 256>>>(out);
}

// round 11
// speedup vs baseline: 2.4233x; 2.4233x over previous
#include <cuda_runtime.h>
#include <cuda_bf16.h>
#include <cstdint>

// Problem constants
#define N_NODES 50000
#define D 256
#define E_EDGES 150000
#define M_DIR (2 * E_EDGES)
#define INV_SCALE 0.125f   // 1/sqrt(64)

// -------- scratch (device globals; no allocations allowed) --------
// Phase 1: g_TV[r] holds T_r = S @ P_r      (used by k_score)
// Phase 2: g_TV[r] holds V_r = S @ W_r^T    (used by k_agg) — same storage, reused
__device__ float g_TV[3][N_NODES * D];          // ~154 MB
__device__ float g_P[3][D * D];                 // P_r[m][k] = sum_c WQ[c][k]*WK[c][m]
__device__ float g_Ee[3][M_DIR];                // exp(score) per directed edge
__device__ float g_z[3][N_NODES];               // softmax denominators
// bf16 split operands for tensor-core GEMM
__device__ __nv_bfloat16 g_Sh[N_NODES * D];     // 25.6 MB
__device__ __nv_bfloat16 g_Sl[N_NODES * D];     // 25.6 MB
__device__ __nv_bfloat16 g_Bh[6][D * D];        // z<3: P_z ; z>=3: W_{z-3}
__device__ __nv_bfloat16 g_Bl[6][D * D];

// ================= K0: zero output + z =================
__global__ void k_init(float* __restrict__ out) {
    int i = blockIdx.x * blockDim.x + threadIdx.x;
    if (i < N_NODES * D) out[i] = 0.0f;
    if (i < 3 * N_NODES) (&g_z[0][0])[i] = 0.0f;
}

// ================= K1: P_r = WQ^T @ WK (fp32, tiny) =================
__global__ void k_mat(const float* __restrict__ WQ, const float* __restrict__ WK) {
    int r = blockIdx.z;
    int mBase = blockIdx.y * 16, kBase = blockIdx.x * 16;
    int ty = threadIdx.y, tx = threadIdx.x;
    __shared__ float aq[16][17];
    __shared__ float ak[16][17];
    const float* wq = WQ + r * D * D;
    const float* wk = WK + r * D * D;
    float acc = 0.0f;
    for (int c0 = 0; c0 < D; c0 += 16) {
        aq[ty][tx] = wq[(c0 + ty) * D + kBase + tx];
        ak[ty][tx] = wk[(c0 + ty) * D + mBase + tx];
        __syncthreads();
#pragma unroll
        for (int cc = 0; cc < 16; cc++)
            acc += ak[cc][ty] * aq[cc][tx];
        __syncthreads();
    }
    g_P[r][(mBase + ty) * D + kBase + tx] = acc;
}

// ================= K1b: fp32 -> bf16 hi/lo splits =================
__global__ void k_convS(const float* __restrict__ S) {
    int i = blockIdx.x * blockDim.x + threadIdx.x;
    if (i >= N_NODES * D) return;
    float x = S[i];
    __nv_bfloat16 h = __float2bfloat16(x);
    g_Sh[i] = h;
    g_Sl[i] = __float2bfloat16(x - __bfloat162float(h));
}
__global__ void k_convB(const float* __restrict__ W) {
    int i = blockIdx.x * blockDim.x + threadIdx.x;
    if (i >= 6 * D * D) return;
    int z = i / (D * D);
    int j = i % (D * D);
    float x = (z < 3) ? g_P[z][j] : W[(size_t)(z - 3) * D * D + j];
    __nv_bfloat16 h = __float2bfloat16(x);
    (&g_Bh[0][0])[i] = h;
    (&g_Bl[0][0])[i] = __float2bfloat16(x - __bfloat162float(h));
}

// ================= mma.sync helpers (compute_80-level; compiles at compute_103) ====
__device__ __forceinline__ void mma_bf16(float* c, uint32_t a0, uint32_t a1, uint32_t a2,
                                         uint32_t a3, uint32_t b0, uint32_t b1) {
    asm volatile(
        "mma.sync.aligned.m16n8k16.row.col.f32.bf16.bf16.f32 "
        "{%0,%1,%2,%3}, {%4,%5,%6,%7}, {%8,%9}, {%0,%1,%2,%3};"
        : "+f"(c[0]), "+f"(c[1]), "+f"(c[2]), "+f"(c[3])
        : "r"(a0), "r"(a1), "r"(a2), "r"(a3), "r"(b0), "r"(b1));
}
__device__ __forceinline__ void ldm_x4(uint32_t* r, uint32_t saddr) {
    asm volatile("ldmatrix.sync.aligned.m8n8.x4.shared.b16 {%0,%1,%2,%3}, [%4];"
                 : "=r"(r[0]), "=r"(r[1]), "=r"(r[2]), "=r"(r[3]) : "r"(saddr));
}
__device__ __forceinline__ void ldm_x2(uint32_t* r, uint32_t saddr) {
    asm volatile("ldmatrix.sync.aligned.m8n8.x2.shared.b16 {%0,%1}, [%2];"
                 : "=r"(r[0]), "=r"(r[1]) : "r"(saddr));
}

// ================= K2: HMMA GEMM, C[128 x 128] per CTA ====================
// C = Ah*Bh + Ah*Bl + Al*Bh, fp32 accumulation in registers.
// A = S rows [m][k] row-major; B = g_B*[z] [n][k] (= col-major k x n). k-contig both.
#define BK 32
#define LDS_STRIDE 40   // 32 + 8 pad elements -> 80B row stride, conflict-free ldmatrix

__global__ void __launch_bounds__(256) k_gemm_tc(int zbase) {
    __shared__ __nv_bfloat16 sAh[128 * LDS_STRIDE];
    __shared__ __nv_bfloat16 sAl[128 * LDS_STRIDE];
    __shared__ __nv_bfloat16 sBh[128 * LDS_STRIDE];
    __shared__ __nv_bfloat16 sBl[128 * LDS_STRIDE];

    int tid = threadIdx.x;
    int wid = tid >> 5;
    int lane = tid & 31;
    int warpM = wid & 3;          // 4 warps along M (32 rows each)
    int warpN = wid >> 2;         // 2 warps along N (64 cols each)

    int r = blockIdx.z;
    int z = zbase + r;
    int rowBase = blockIdx.x * 128;
    int colBase = blockIdx.y * 128;

    const __nv_bfloat16* Bh = g_Bh[z];
    const __nv_bfloat16* Bl = g_Bl[z];

    float acc[2][8][4];
#pragma unroll
    for (int mt = 0; mt < 2; mt++)
#pragma unroll
        for (int nt = 0; nt < 8; nt++)
#pragma unroll
            for (int j = 0; j < 4; j++) acc[mt][nt][j] = 0.0f;

    // ldmatrix shared addresses (lane-dependent, loop-invariant parts)
    // A x4: t0-7 rows0-7@k0 | t8-15 rows8-15@k0 | t16-23 rows0-7@k8 | t24-31 rows8-15@k8
    int aRow = (lane & 15);
    int aKh  = (lane >> 4) * 8;
    // B x2: t0-7 n-rows0-7@k0 | t8-15 n-rows0-7@k8 (threads>=16 unused, safe addr)
    int bRow = (lane & 7);
    int bKh  = ((lane >> 3) & 1) * 8;

    uint32_t sAh_b = (uint32_t)__cvta_generic_to_shared(sAh);
    uint32_t sAl_b = (uint32_t)__cvta_generic_to_shared(sAl);
    uint32_t sBh_b = (uint32_t)__cvta_generic_to_shared(sBh);
    uint32_t sBl_b = (uint32_t)__cvta_generic_to_shared(sBl);

    for (int k0 = 0; k0 < D; k0 += BK) {
        // ---- stage A (hi+lo) and B (hi+lo): 128 rows x 32 bf16 each ----
#pragma unroll
        for (int i = tid; i < 512; i += 256) {
            int row = i >> 2, c = i & 3;             // c: 8-elem (16B) chunk
            int sidx = row * LDS_STRIDE + c * 8;
            int gr = rowBase + row;
            uint4 vh = make_uint4(0, 0, 0, 0), vl = make_uint4(0, 0, 0, 0);
            if (gr < N_NODES) {
                size_t off = (size_t)gr * D + k0 + c * 8;
                vh = *(const uint4*)(g_Sh + off);
                vl = *(const uint4*)(g_Sl + off);
            }
            *(uint4*)(sAh + sidx) = vh;
            *(uint4*)(sAl + sidx) = vl;

            size_t boff = (size_t)(colBase + row) * D + k0 + c * 8;
            *(uint4*)(sBh + sidx) = *(const uint4*)(Bh + boff);
            *(uint4*)(sBl + sidx) = *(const uint4*)(Bl + boff);
        }
        __syncthreads();

        // ---- compute: 2 k-steps of 16 ----
#pragma unroll
        for (int kk = 0; kk < BK; kk += 16) {
            uint32_t ah[2][4], al[2][4];
#pragma unroll
            for (int mt = 0; mt < 2; mt++) {
                int rr = warpM * 32 + mt * 16 + aRow;
                uint32_t off = (uint32_t)((rr * LDS_STRIDE + kk + aKh) * 2);
                ldm_x4(ah[mt], sAh_b + off);
                ldm_x4(al[mt], sAl_b + off);
            }
#pragma unroll
            for (int nt = 0; nt < 8; nt++) {
                int nn = warpN * 64 + nt * 8 + bRow;
                uint32_t off = (uint32_t)((nn * LDS_STRIDE + kk + bKh) * 2);
                uint32_t bh[2], bl[2];
                ldm_x2(bh, sBh_b + off);
                ldm_x2(bl, sBl_b + off);
#pragma unroll
                for (int mt = 0; mt < 2; mt++) {
                    mma_bf16(acc[mt][nt], ah[mt][0], ah[mt][1], ah[mt][2], ah[mt][3], bh[0], bh[1]);
                    mma_bf16(acc[mt][nt], ah[mt][0], ah[mt][1], ah[mt][2], ah[mt][3], bl[0], bl[1]);
                    mma_bf16(acc[mt][nt], al[mt][0], al[mt][1], al[mt][2], al[mt][3], bh[0], bh[1]);
                }
            }
        }
        __syncthreads();
    }

    // ---- epilogue: C fragments -> global fp32 ----
    float* C = g_TV[r];
#pragma unroll
    for (int mt = 0; mt < 2; mt++) {
        int r0 = rowBase + warpM * 32 + mt * 16 + (lane >> 2);
        int r1 = r0 + 8;
#pragma unroll
        for (int nt = 0; nt < 8; nt++) {
            int col = colBase + warpN * 64 + nt * 8 + (lane & 3) * 2;
            if (r0 < N_NODES)
                *(float2*)(C + (size_t)r0 * D + col) = make_float2(acc[mt][nt][0], acc[mt][nt][1]);
            if (r1 < N_NODES)
                *(float2*)(C + (size_t)r1 * D + col) = make_float2(acc[mt][nt][2], acc[mt][nt][3]);
        }
    }
}

// ================= K3: edge scores -> exp -> z =================
__global__ void __launch_bounds__(256) k_score(const float* __restrict__ S,
                                               const int* __restrict__ e_t,
                                               const int* __restrict__ e_c,
                                               const int* __restrict__ e_s) {
    int r = blockIdx.y;
    const int* edges = (r == 0) ? e_t : (r == 1) ? e_c : e_s;
    int warp = blockIdx.x * (blockDim.x >> 5) + (threadIdx.x >> 5);
    int lane = threadIdx.x & 31;
    if (warp >= E_EDGES) return;

    int a = edges[2 * warp];
    int b = edges[2 * warp + 1];
    const float* T  = g_TV[r];
    const float* Ta = T + (size_t)a * D;
    const float* Tb = T + (size_t)b * D;
    const float* Sa = S + (size_t)a * D;
    const float* Sb = S + (size_t)b * D;

    float s_ab = 0.f, s_ba = 0.f;
#pragma unroll
    for (int c = 0; c < 2; c++) {
        int d = c * 128 + lane * 4;
        float4 ta = *(const float4*)(Ta + d);
        float4 sb = *(const float4*)(Sb + d);
        float4 tb = *(const float4*)(Tb + d);
        float4 sa = *(const float4*)(Sa + d);
        s_ab += ta.x * sb.x + ta.y * sb.y + ta.z * sb.z + ta.w * sb.w;
        s_ba += tb.x * sa.x + tb.y * sa.y + tb.z * sa.z + tb.w * sa.w;
    }
#pragma unroll
    for (int o = 16; o > 0; o >>= 1) {
        s_ab += __shfl_xor_sync(0xffffffff, s_ab, o);
        s_ba += __shfl_xor_sync(0xffffffff, s_ba, o);
    }
    if (lane == 0) {
        float eab = expf(s_ab * INV_SCALE);
        float eba = expf(s_ba * INV_SCALE);
        g_Ee[r][warp]           = eab;
        g_Ee[r][E_EDGES + warp] = eba;
        atomicAdd(&g_z[r][a], eab);
        atomicAdd(&g_z[r][b], eba);
    }
}

// ================= K4: aggregation =================
__global__ void __launch_bounds__(256) k_agg(float* __restrict__ out,
                                             const int* __restrict__ e_t,
                                             const int* __restrict__ e_c,
                                             const int* __restrict__ e_s) {
    int r = blockIdx.y;
    const int* edges = (r == 0) ? e_t : (r == 1) ? e_c : e_s;
    int warp = blockIdx.x * (blockDim.x >> 5) + (threadIdx.x >> 5);
    int lane = threadIdx.x & 31;
    if (warp >= M_DIR) return;

    int rec, nbr;
    if (warp < E_EDGES) {
        rec = edges[2 * warp];
        nbr = edges[2 * warp + 1];
    } else {
        int e = warp - E_EDGES;
        rec = edges[2 * e + 1];
        nbr = edges[2 * e];
    }
    float alpha = g_Ee[r][warp] / g_z[r][rec];

    const float* V = g_TV[r] + (size_t)nbr * D;
    float* O = out + (size_t)rec * D;
#pragma unroll
    for (int c = 0; c < 2; c++) {
        int d = c * 128 + lane * 4;
        float4 v = *(const float4*)(V + d);
        float4 addv = make_float4(alpha * v.x, alpha * v.y, alpha * v.z, alpha * v.w);
        atomicAdd((float4*)(O + d), addv);
    }
}

// ================= K5: relu =================
__global__ void k_relu(float* __restrict__ out) {
    int i = blockIdx.x * blockDim.x + threadIdx.x;
    if (i < N_NODES * D) out[i] = fmaxf(out[i], 0.0f);
}

extern "C" void kernel_launch(void* const* d_in, const int* in_sizes, int n_in,
                              void* d_out, int out_size) {
    const float* S  = (const float*)d_in[0];
    const int*   et = (const int*)d_in[1];
    const int*   ec = (const int*)d_in[2];
    const int*   es = (const int*)d_in[3];
    const float* W  = (const float*)d_in[4];
    const float* WQ = (const float*)d_in[5];
    const float* WK = (const float*)d_in[6];
    float* out = (float*)d_out;

    // K0: zero out + z
    k_init<<<(N_NODES * D + 255) / 256, 256>>>(out);

    // K1: P_r = WQ_r^T @ WK_r (fp32, tiny)
    {
        dim3 g(D / 16, D / 16, 3), b(16, 16);
        k_mat<<<g, b>>>(WQ, WK);
    }

    // K1b: bf16 hi/lo splits
    k_convS<<<(N_NODES * D + 255) / 256, 256>>>(S);
    k_convB<<<(6 * D * D + 255) / 256, 256>>>(W);

    dim3 gg((N_NODES + 127) / 128, D / 128, 3);

    // K2a: T_r = S @ P_r (HMMA tensor cores)
    k_gemm_tc<<<gg, 256>>>(0);

    // K3: edge scores -> exp -> z (consumes T)
    {
        dim3 g((E_EDGES + 7) / 8, 3);
        k_score<<<g, 256>>>(S, et, ec, es);
    }

    // K2b: V_r = S @ W_r^T (overwrites g_TV)
    k_gemm_tc<<<gg, 256>>>(3);

    // K4: weighted aggregation (consumes V)
    {
        dim3 g((M_DIR + 7) / 8, 3);
        k_agg<<<g, 256>>>(out, et, ec, es);
    }

    // K5: relu
    k_relu<<<(N_NODES * D + 255) / 256, 256>>>(out);
}

// round 14
// speedup vs baseline: 2.5949x; 1.0708x over previous
#include <cuda_runtime.h>
#include <cuda_bf16.h>
#include <cstdint>

// Problem constants
#define N_NODES 50000
#define D 256
#define E_EDGES 150000
#define M_DIR (2 * E_EDGES)
#define INV_SCALE 0.125f   // 1/sqrt(64)

// -------- scratch (device globals; no allocations allowed) --------
__device__ float g_TV[3][N_NODES * D];          // phase1: T_r ; phase2: V_r
__device__ float g_P[3][D * D];                 // P_r[m][k] = sum_c WQ[c][k]*WK[c][m]
__device__ float g_Ee[3][M_DIR];                // exp(score) per directed edge
__device__ float g_z[3][N_NODES];               // softmax denominators
__device__ __nv_bfloat16 g_Sh[N_NODES * D];
__device__ __nv_bfloat16 g_Sl[N_NODES * D];
__device__ __nv_bfloat16 g_Bh[6][D * D];        // z<3: P_z ; z>=3: W_{z-3}
__device__ __nv_bfloat16 g_Bl[6][D * D];

// ================= K0: zero output + z =================
__global__ void k_init(float* __restrict__ out) {
    int i = blockIdx.x * blockDim.x + threadIdx.x;
    if (i < N_NODES * D) out[i] = 0.0f;
    if (i < 3 * N_NODES) (&g_z[0][0])[i] = 0.0f;
}

// ================= K1: P_r = WQ^T @ WK (fp32, tiny) =================
__global__ void k_mat(const float* __restrict__ WQ, const float* __restrict__ WK) {
    int r = blockIdx.z;
    int mBase = blockIdx.y * 16, kBase = blockIdx.x * 16;
    int ty = threadIdx.y, tx = threadIdx.x;
    __shared__ float aq[16][17];
    __shared__ float ak[16][17];
    const float* wq = WQ + r * D * D;
    const float* wk = WK + r * D * D;
    float acc = 0.0f;
    for (int c0 = 0; c0 < D; c0 += 16) {
        aq[ty][tx] = wq[(c0 + ty) * D + kBase + tx];
        ak[ty][tx] = wk[(c0 + ty) * D + mBase + tx];
        __syncthreads();
#pragma unroll
        for (int cc = 0; cc < 16; cc++)
            acc += ak[cc][ty] * aq[cc][tx];
        __syncthreads();
    }
    g_P[r][(mBase + ty) * D + kBase + tx] = acc;
}

// ================= K1b: fp32 -> bf16 hi/lo splits =================
__global__ void k_convS(const float* __restrict__ S) {
    int i = blockIdx.x * blockDim.x + threadIdx.x;
    if (i >= N_NODES * D) return;
    float x = S[i];
    __nv_bfloat16 h = __float2bfloat16(x);
    g_Sh[i] = h;
    g_Sl[i] = __float2bfloat16(x - __bfloat162float(h));
}
__global__ void k_convB(const float* __restrict__ W) {
    int i = blockIdx.x * blockDim.x + threadIdx.x;
    if (i >= 6 * D * D) return;
    int z = i / (D * D);
    int j = i % (D * D);
    float x = (z < 3) ? g_P[z][j] : W[(size_t)(z - 3) * D * D + j];
    __nv_bfloat16 h = __float2bfloat16(x);
    (&g_Bh[0][0])[i] = h;
    (&g_Bl[0][0])[i] = __float2bfloat16(x - __bfloat162float(h));
}

// ================= mma.sync / ldmatrix / cp.async helpers =================
__device__ __forceinline__ void mma_bf16(float* c, uint32_t a0, uint32_t a1, uint32_t a2,
                                         uint32_t a3, uint32_t b0, uint32_t b1) {
    asm volatile(
        "mma.sync.aligned.m16n8k16.row.col.f32.bf16.bf16.f32 "
        "{%0,%1,%2,%3}, {%4,%5,%6,%7}, {%8,%9}, {%0,%1,%2,%3};"
        : "+f"(c[0]), "+f"(c[1]), "+f"(c[2]), "+f"(c[3])
        : "r"(a0), "r"(a1), "r"(a2), "r"(a3), "r"(b0), "r"(b1));
}
__device__ __forceinline__ void ldm_x4(uint32_t* r, uint32_t saddr) {
    asm volatile("ldmatrix.sync.aligned.m8n8.x4.shared.b16 {%0,%1,%2,%3}, [%4];"
                 : "=r"(r[0]), "=r"(r[1]), "=r"(r[2]), "=r"(r[3]) : "r"(saddr));
}
__device__ __forceinline__ void ldm_x2(uint32_t* r, uint32_t saddr) {
    asm volatile("ldmatrix.sync.aligned.m8n8.x2.shared.b16 {%0,%1}, [%2];"
                 : "=r"(r[0]), "=r"(r[1]) : "r"(saddr));
}
// cp.async 16B with zero-fill when srcsize==0
__device__ __forceinline__ void cp16z(uint32_t dst, const void* src, int srcsize) {
    asm volatile("cp.async.cg.shared.global [%0], [%1], 16, %2;"
                 :: "r"(dst), "l"(src), "r"(srcsize) : "memory");
}

// ================= K2: HMMA GEMM, C[128 x 128] per CTA, cp.async double-buffered ===
// C = Ah*Bh + Ah*Bl + Al*Bh, fp32 accumulation in registers.
// A = S rows [m][k] row-major; B = g_B*[z] [n][k] (= col-major k x n). k-contig both.
#define BK 32
#define NC (D / BK)     // 8 K-chunks
#define LDS_STRIDE 40   // 32 + 8 pad elems -> 80B row stride, conflict-free ldmatrix
#define TILE_B (128 * LDS_STRIDE * 2)     // 10240 B per matrix tile
#define OFF_AH 0
#define OFF_AL (TILE_B)
#define OFF_BH (2 * TILE_B)
#define OFF_BL (3 * TILE_B)
#define BUF_B  (4 * TILE_B)               // 40960 B per buffer
#define SMEM_GEMM (2 * BUF_B)             // 81920 B

__global__ void __launch_bounds__(256) k_gemm_tc(int zbase) {
    extern __shared__ char dsm[];
    uint32_t sb = (uint32_t)__cvta_generic_to_shared(dsm);

    int tid = threadIdx.x;
    int wid = tid >> 5;
    int lane = tid & 31;
    int warpM = wid & 3;          // 4 warps along M (32 rows each)
    int warpN = wid >> 2;         // 2 warps along N (64 cols each)

    int r = blockIdx.z;
    int z = zbase + r;
    int rowBase = blockIdx.x * 128;
    int colBase = blockIdx.y * 128;

    const __nv_bfloat16* Bh = g_Bh[z];
    const __nv_bfloat16* Bl = g_Bl[z];

    float acc[2][8][4];
#pragma unroll
    for (int mt = 0; mt < 2; mt++)
#pragma unroll
        for (int nt = 0; nt < 8; nt++)
#pragma unroll
            for (int j = 0; j < 4; j++) acc[mt][nt][j] = 0.0f;

    // ldmatrix lane-dependent offsets
    int aRow = (lane & 15);
    int aKh  = (lane >> 4) * 8;
    int bRow = (lane & 7);
    int bKh  = ((lane >> 3) & 1) * 8;

    // stage K-chunk c into buffer buf via cp.async (8 x 16B per thread)
    auto stage = [&](int c, int buf) {
        int k0 = c * BK;
        uint32_t base = sb + buf * BUF_B;
#pragma unroll
        for (int i = tid; i < 512; i += 256) {
            int row = i >> 2, ch = i & 3;
            uint32_t so = (uint32_t)(row * LDS_STRIDE + ch * 8) * 2;
            int gr = rowBase + row;
            int ok = (gr < N_NODES);
            size_t aoff = (size_t)(ok ? gr : 0) * D + k0 + ch * 8;
            cp16z(base + OFF_AH + so, g_Sh + aoff, ok ? 16 : 0);
            cp16z(base + OFF_AL + so, g_Sl + aoff, ok ? 16 : 0);
            size_t boff = (size_t)(colBase + row) * D + k0 + ch * 8;
            cp16z(base + OFF_BH + so, Bh + boff, 16);
            cp16z(base + OFF_BL + so, Bl + boff, 16);
        }
        asm volatile("cp.async.commit_group;" ::: "memory");
    };

    stage(0, 0);

    for (int c = 0; c < NC; c++) {
        int buf = c & 1;
        if (c + 1 < NC) {
            stage(c + 1, buf ^ 1);
            asm volatile("cp.async.wait_group 1;" ::: "memory");
        } else {
            asm volatile("cp.async.wait_group 0;" ::: "memory");
        }
        __syncthreads();

        uint32_t base = sb + buf * BUF_B;
#pragma unroll
        for (int kk = 0; kk < BK; kk += 16) {
            uint32_t ah[2][4], al[2][4];
#pragma unroll
            for (int mt = 0; mt < 2; mt++) {
                int rr = warpM * 32 + mt * 16 + aRow;
                uint32_t off = (uint32_t)((rr * LDS_STRIDE + kk + aKh) * 2);
                ldm_x4(ah[mt], base + OFF_AH + off);
                ldm_x4(al[mt], base + OFF_AL + off);
            }
#pragma unroll
            for (int nt = 0; nt < 8; nt++) {
                int nn = warpN * 64 + nt * 8 + bRow;
                uint32_t off = (uint32_t)((nn * LDS_STRIDE + kk + bKh) * 2);
                uint32_t bh[2], bl[2];
                ldm_x2(bh, base + OFF_BH + off);
                ldm_x2(bl, base + OFF_BL + off);
#pragma unroll
                for (int mt = 0; mt < 2; mt++) {
                    mma_bf16(acc[mt][nt], ah[mt][0], ah[mt][1], ah[mt][2], ah[mt][3], bh[0], bh[1]);
                    mma_bf16(acc[mt][nt], ah[mt][0], ah[mt][1], ah[mt][2], ah[mt][3], bl[0], bl[1]);
                    mma_bf16(acc[mt][nt], al[mt][0], al[mt][1], al[mt][2], al[mt][3], bh[0], bh[1]);
                }
            }
        }
        __syncthreads();
    }

    // ---- epilogue: C fragments -> global fp32 ----
    float* C = g_TV[r];
#pragma unroll
    for (int mt = 0; mt < 2; mt++) {
        int r0 = rowBase + warpM * 32 + mt * 16 + (lane >> 2);
        int r1 = r0 + 8;
#pragma unroll
        for (int nt = 0; nt < 8; nt++) {
            int col = colBase + warpN * 64 + nt * 8 + (lane & 3) * 2;
            if (r0 < N_NODES)
                *(float2*)(C + (size_t)r0 * D + col) = make_float2(acc[mt][nt][0], acc[mt][nt][1]);
            if (r1 < N_NODES)
                *(float2*)(C + (size_t)r1 * D + col) = make_float2(acc[mt][nt][2], acc[mt][nt][3]);
        }
    }
}

// ================= K3: edge scores -> exp -> z (relation-major 1D grid) =================
#define SC_BLOCKS ((E_EDGES + 7) / 8)
__global__ void __launch_bounds__(256) k_score(const float* __restrict__ S,
                                               const int* __restrict__ e_t,
                                               const int* __restrict__ e_c,
                                               const int* __restrict__ e_s) {
    int r = blockIdx.x / SC_BLOCKS;
    int blk = blockIdx.x - r * SC_BLOCKS;
    const int* edges = (r == 0) ? e_t : (r == 1) ? e_c : e_s;
    int warp = blk * 8 + (threadIdx.x >> 5);
    int lane = threadIdx.x & 31;
    if (warp >= E_EDGES) return;

    int a = edges[2 * warp];
    int b = edges[2 * warp + 1];
    const float* T  = g_TV[r];
    const float* Ta = T + (size_t)a * D;
    const float* Tb = T + (size_t)b * D;
    const float* Sa = S + (size_t)a * D;
    const float* Sb = S + (size_t)b * D;

    float s_ab = 0.f, s_ba = 0.f;
#pragma unroll
    for (int c = 0; c < 2; c++) {
        int d = c * 128 + lane * 4;
        float4 ta = *(const float4*)(Ta + d);
        float4 sb = *(const float4*)(Sb + d);
        float4 tb = *(const float4*)(Tb + d);
        float4 sa = *(const float4*)(Sa + d);
        s_ab += ta.x * sb.x + ta.y * sb.y + ta.z * sb.z + ta.w * sb.w;
        s_ba += tb.x * sa.x + tb.y * sa.y + tb.z * sa.z + tb.w * sa.w;
    }
#pragma unroll
    for (int o = 16; o > 0; o >>= 1) {
        s_ab += __shfl_xor_sync(0xffffffff, s_ab, o);
        s_ba += __shfl_xor_sync(0xffffffff, s_ba, o);
    }
    if (lane == 0) {
        float eab = expf(s_ab * INV_SCALE);
        float eba = expf(s_ba * INV_SCALE);
        g_Ee[r][warp]           = eab;
        g_Ee[r][E_EDGES + warp] = eba;
        atomicAdd(&g_z[r][a], eab);
        atomicAdd(&g_z[r][b], eba);
    }
}

// ================= K4: aggregation (relation-major 1D grid) =================
#define AG_BLOCKS ((M_DIR + 7) / 8)
__global__ void __launch_bounds__(256) k_agg(float* __restrict__ out,
                                             const int* __restrict__ e_t,
                                             const int* __restrict__ e_c,
                                             const int* __restrict__ e_s) {
    int r = blockIdx.x / AG_BLOCKS;
    int blk = blockIdx.x - r * AG_BLOCKS;
    const int* edges = (r == 0) ? e_t : (r == 1) ? e_c : e_s;
    int warp = blk * 8 + (threadIdx.x >> 5);
    int lane = threadIdx.x & 31;
    if (warp >= M_DIR) return;

    int rec, nbr;
    if (warp < E_EDGES) {
        rec = edges[2 * warp];
        nbr = edges[2 * warp + 1];
    } else {
        int e = warp - E_EDGES;
        rec = edges[2 * e + 1];
        nbr = edges[2 * e];
    }
    float alpha = g_Ee[r][warp] / g_z[r][rec];

    const float* V = g_TV[r] + (size_t)nbr * D;
    float* O = out + (size_t)rec * D;
#pragma unroll
    for (int c = 0; c < 2; c++) {
        int d = c * 128 + lane * 4;
        float4 v = *(const float4*)(V + d);
        float4 addv = make_float4(alpha * v.x, alpha * v.y, alpha * v.z, alpha * v.w);
        atomicAdd((float4*)(O + d), addv);
    }
}

// ================= K5: relu =================
__global__ void k_relu(float* __restrict__ out) {
    int i = blockIdx.x * blockDim.x + threadIdx.x;
    if (i < N_NODES * D) out[i] = fmaxf(out[i], 0.0f);
}

extern "C" void kernel_launch(void* const* d_in, const int* in_sizes, int n_in,
                              void* d_out, int out_size) {
    const float* S  = (const float*)d_in[0];
    const int*   et = (const int*)d_in[1];
    const int*   ec = (const int*)d_in[2];
    const int*   es = (const int*)d_in[3];
    const float* W  = (const float*)d_in[4];
    const float* WQ = (const float*)d_in[5];
    const float* WK = (const float*)d_in[6];
    float* out = (float*)d_out;

    static int smem_set = 0;
    if (!smem_set) {
        cudaFuncSetAttribute(k_gemm_tc, cudaFuncAttributeMaxDynamicSharedMemorySize, SMEM_GEMM);
        smem_set = 1;
    }

    // K0: zero out + z
    k_init<<<(N_NODES * D + 255) / 256, 256>>>(out);

    // K1: P_r = WQ_r^T @ WK_r (fp32, tiny)
    {
        dim3 g(D / 16, D / 16, 3), b(16, 16);
        k_mat<<<g, b>>>(WQ, WK);
    }

    // K1b: bf16 hi/lo splits
    k_convS<<<(N_NODES * D + 255) / 256, 256>>>(S);
    k_convB<<<(6 * D * D + 255) / 256, 256>>>(W);

    dim3 gg((N_NODES + 127) / 128, D / 128, 3);

    // K2a: T_r = S @ P_r (HMMA, double-buffered)
    k_gemm_tc<<<gg, 256, SMEM_GEMM>>>(0);

    // K3: edge scores -> exp -> z (consumes T)
    k_score<<<3 * SC_BLOCKS, 256>>>(S, et, ec, es);

    // K2b: V_r = S @ W_r^T (overwrites g_TV)
    k_gemm_tc<<<gg, 256, SMEM_GEMM>>>(3);

    // K4: weighted aggregation (consumes V)
    k_agg<<<3 * AG_BLOCKS, 256>>>(out, et, ec, es);

    // K5: relu
    k_relu<<<(N_NODES * D + 255) / 256, 256>>>(out);
}